// round 10
// baseline (speedup 1.0000x reference)
#include <cuda_runtime.h>
#include <cstdint>

typedef unsigned long long ull;

// ---- packed f32x2 helpers: per-lane IEEE fp32 semantics ----
__device__ __forceinline__ ull fma2(ull a, ull b, ull c) {
    ull d;
    asm("fma.rn.f32x2 %0, %1, %2, %3;" : "=l"(d) : "l"(a), "l"(b), "l"(c));
    return d;
}
__device__ __forceinline__ ull add2(ull a, ull b) {
    ull d;
    asm("add.rn.f32x2 %0, %1, %2;" : "=l"(d) : "l"(a), "l"(b));
    return d;
}
__device__ __forceinline__ float ulo(ull v) { return __uint_as_float((unsigned)v); }
__device__ __forceinline__ float uhi(ull v) { return __uint_as_float((unsigned)(v >> 32)); }
__device__ __forceinline__ ull dup2a(float x) {
    ull d;
    asm("mov.b64 %0, {%1, %1};" : "=l"(d) : "f"(x));
    return d;
}
__device__ __forceinline__ ull dup2(float x) {
    unsigned u = __float_as_uint(x);
    return ((ull)u << 32) | (ull)u;
}

static constexpr int D       = 64;
static constexpr int HW      = 4096;
static constexpr int K       = 512;
static constexpr int N_VEC   = 131072;
static constexpr int N_ELEMS = N_VEC * D;         // 8388608
static constexpr int LOSS_OFF = N_ELEMS;
static constexpr int IDX_OFF  = N_ELEMS + 1;
static constexpr int THREADS  = 512;
static constexpr int NCTA     = 148;
static constexpr int VTILE    = 128;              // vectors per CTA-tile
static constexpr int NTILE    = N_VEC / VTILE;    // 1024

// smem layout (floats)
static constexpr int OFF_T  = 0;                  // sT  [64][512]
static constexpr int OFF_E  = 32768;              // sE  [512]
static constexpr int OFF_X  = 33280;              // sX  [2][64][128] double-buffered
static constexpr int OFF_SL = 49664;              // sSl [2][4][128] S-lane partials
static constexpr int OFF_B  = 50688;              // sB  [128]
static constexpr int OFF_CD = 50816;              // sCd [128][16]
static constexpr int OFF_CI = 52864;              // sCi [128][16]
static constexpr int SMEM_FLOATS = 54912;
static constexpr int SMEM_BYTES  = SMEM_FLOATS * 4;   // 219648

__device__ double   g_loss = 0.0;
__device__ unsigned g_done = 0u;

// Persistent: 148 CTAs x 512 threads; CTA tile = 128 vec x 512 codes, double-buffered.
// tv=tid&31 (4 vecs), tk=tid>>5 (32 codes in 2 passes of 8 pairs).
// Staging fuses the S-lane partials (thread covers d == dg (mod 4), ascending -> one XLA lane).
// Next tile's LDGs issue before current gather/store (latency hidden; accs dead -> no spill).
// EXACT-INVARIANT (verified rel_err==0.0 six times, do not change):
//   d_k  = fl32( fl32(S + E_k) + (-2)*dot_k )
//   dot_k = strict sequential fp32 FMA chain over d=0..63
//   S     = 4-lane stride-4 sums combined (l0+l2)+(l1+l3)
//   argmin: strict '<', first-min ascending k (lane0<lane1; asc c; asc pass; asc tk)
//   out   = fl(x + fl(q - x))
__global__ __launch_bounds__(THREADS, 1)
void k_main(const float* __restrict__ in, const float* __restrict__ emb,
            float* __restrict__ out, int write_extras) {
    extern __shared__ float s[];
    float* sT = s + OFF_T;
    float* sE = s + OFF_E;
    float* sX = s + OFF_X;    // [2][64][128]
    float* sSl = s + OFF_SL;  // [2][4][128]
    int*   sB = (int*)(s + OFF_B);
    float* sCd = s + OFF_CD;
    int*   sCi = (int*)(s + OFF_CI);
    __shared__ double red[16];

    const int tid = threadIdx.x;
    const int tv  = tid & 31;    // 4 vecs [tv*4, tv*4+3]
    const int tk  = tid >> 5;    // 32 codes [tk*32, tk*32+31]
    const int vv  = tid & 127;   // staging/gather vector
    const int dg  = tid >> 7;    // staging d-group (d == dg mod 4)

    // ---- stage codebook TRANSPOSED ----
#pragma unroll
    for (int i = 0; i < 64; i++) {
        int lin = i * THREADS + tid;
        int k = lin & 511;
        int d = lin >> 9;
        sT[d * K + k] = emb[k * D + d];
    }

    // ---- E_k: XLA 4-lane pattern, 1 code/thread ----
    {
        const float* r = emb + tid * D;
        float l0 = 0.f, l1 = 0.f, l2 = 0.f, l3 = 0.f;
#pragma unroll
        for (int i = 0; i < 16; i++) {
            l0 = __fadd_rn(l0, __fmul_rn(r[4 * i + 0], r[4 * i + 0]));
            l1 = __fadd_rn(l1, __fmul_rn(r[4 * i + 1], r[4 * i + 1]));
            l2 = __fadd_rn(l2, __fmul_rn(r[4 * i + 2], r[4 * i + 2]));
            l3 = __fadd_rn(l3, __fmul_rn(r[4 * i + 3], r[4 * i + 3]));
        }
        sE[tid] = __fadd_rn(__fadd_rn(l0, l2), __fadd_rn(l1, l3));
    }

    const ull NEG2 = dup2(-2.0f);
    float lsumf = 0.0f;
    int bf = 0;

    // ---- prologue: stage first tile into buffer 0 (fused S partials) ----
    int tile = blockIdx.x;
    {
        const int v0 = tile * VTILE;
        const float* xg = in + (v0 >> 12) * (D * HW) + (v0 & 4095) + vv;
        float l = 0.f;
        float* dst = sX + 0 * 8192;
#pragma unroll
        for (int i = 0; i < 16; i++) {
            const int d = 4 * i + dg;
            float x = xg[d * HW];
            dst[d * VTILE + vv] = x;
            l = __fadd_rn(l, __fmul_rn(x, x));
        }
        sSl[0 * 512 + dg * 128 + vv] = l;
    }
    __syncthreads();

    for (; tile < NTILE; tile += NCTA, bf ^= 1) {
        const int v0 = tile * VTILE;
        const int b  = v0 >> 12;
        const int p  = v0 & 4095;
        const int nt = tile + NCTA;
        const bool has_next = nt < NTILE;
        float* sXb = sX + bf * 8192;

        // ---- S for my 4 vecs (local combine of staged lane partials) ----
        const float* sl = sSl + bf * 512;
        ull Sd[4];
#pragma unroll
        for (int vp = 0; vp < 4; vp++) {
            const int vec = tv * 4 + vp;
            float Sv = __fadd_rn(__fadd_rn(sl[0 * 128 + vec], sl[2 * 128 + vec]),
                                 __fadd_rn(sl[1 * 128 + vec], sl[3 * 128 + vec]));
            Sd[vp] = dup2(Sv);
        }

        // ---- per-vec running best across both k-passes ----
        float bestD[4];
        int   bestI[4];
#pragma unroll
        for (int vp = 0; vp < 4; vp++) { bestD[vp] = 3.4e38f; bestI[vp] = 0; }

        for (int pass = 0; pass < 2; pass++) {
            const int kb = tk * 32 + pass * 16;
            ull acc[32];
#pragma unroll
            for (int i = 0; i < 32; i++) acc[i] = 0ull;

            const float* xp = sXb + tv * 4;
            const float* ep = sT + kb;

            float4 xv = *(const float4*)(xp);
            ulonglong2 E0 = ((const ulonglong2*)ep)[0];
            ulonglong2 E1 = ((const ulonglong2*)ep)[1];
            ulonglong2 E2 = ((const ulonglong2*)ep)[2];
            ulonglong2 E3 = ((const ulonglong2*)ep)[3];

#pragma unroll 2
            for (int d = 0; d < 64; d++) {
                const int dn = (d < 63) ? d + 1 : 63;
                const float* xq = xp + dn * VTILE;
                const ulonglong2* eq = (const ulonglong2*)(ep + dn * K);
                float4 xn = *(const float4*)(xq);
                ulonglong2 N0 = eq[0], N1 = eq[1], N2 = eq[2], N3 = eq[3];

                ull x0 = dup2a(xv.x);
                ull x1 = dup2a(xv.y);
                ull x2 = dup2a(xv.z);
                ull x3 = dup2a(xv.w);
                ull ev[8] = { E0.x, E0.y, E1.x, E1.y, E2.x, E2.y, E3.x, E3.y };
#pragma unroll
                for (int c = 0; c < 8; c++) {
                    acc[0 * 8 + c] = fma2(x0, ev[c], acc[0 * 8 + c]);
                    acc[1 * 8 + c] = fma2(x1, ev[c], acc[1 * 8 + c]);
                    acc[2 * 8 + c] = fma2(x2, ev[c], acc[2 * 8 + c]);
                    acc[3 * 8 + c] = fma2(x3, ev[c], acc[3 * 8 + c]);
                }
                xv = xn; E0 = N0; E1 = N1; E2 = N2; E3 = N3;
            }

            // epilogue: distances + running argmin (ascending k)
            const ull* epE = (const ull*)(sE + kb);
#pragma unroll
            for (int c = 0; c < 8; c++) {
                ull Ec = epE[c];
                const int k0 = kb + 2 * c;
#pragma unroll
                for (int vp = 0; vp < 4; vp++) {
                    ull t1 = add2(Sd[vp], Ec);
                    ull dd = fma2(acc[vp * 8 + c], NEG2, t1);
                    float d0 = ulo(dd), d1 = uhi(dd);
                    if (d0 < bestD[vp]) { bestD[vp] = d0; bestI[vp] = k0; }
                    if (d1 < bestD[vp]) { bestD[vp] = d1; bestI[vp] = k0 + 1; }
                }
            }
        }

        // ---- publish candidates [vec][tk] ----
#pragma unroll
        for (int vp = 0; vp < 4; vp++) {
            const int vvp = tv * 4 + vp;
            sCd[vvp * 16 + tk] = bestD[vp];
            sCi[vvp * 16 + tk] = bestI[vp];
        }
        __syncthreads();

        // ---- final reduce per vec (ascending tk = ascending k) ----
        if (tid < VTILE) {
            float best = 3.4e38f;
            int bi = 0;
#pragma unroll
            for (int t2 = 0; t2 < 16; t2++) {
                float dd = sCd[tid * 16 + t2];
                if (dd < best) { best = dd; bi = sCi[tid * 16 + t2]; }
            }
            sB[tid] = bi;
            if (write_extras) out[IDX_OFF + v0 + tid] = (float)bi;
        }
        __syncthreads();

        // ---- tail: prefetch next tile (LDG), gather/store current, stage next ----
        float r[16];
        if (has_next) {
            const int nv0 = nt * VTILE;
            const float* xg2 = in + (nv0 >> 12) * (D * HW) + (nv0 & 4095) + vv;
#pragma unroll
            for (int i = 0; i < 16; i++) r[i] = xg2[(4 * i + dg) * HW];
        }

        {
            const int d0 = dg * 16;
            const int bi = sB[vv];
            float* og = out + b * (D * HW) + p + vv;
#pragma unroll
            for (int j = 0; j < 16; j++) {
                const int d = d0 + j;
                float q  = sT[d * K + bi];
                float xs = sXb[d * VTILE + vv];
                float t  = __fsub_rn(q, xs);       // fl(q - x)
                og[d * HW] = __fadd_rn(xs, t);     // fl(x + (q - x))
                lsumf = __fmaf_rn(t, t, lsumf);
            }
        }

        if (has_next) {
            float* dst = sX + (bf ^ 1) * 8192;
            float l = 0.f;
#pragma unroll
            for (int i = 0; i < 16; i++) {
                const int d = 4 * i + dg;
                dst[d * VTILE + vv] = r[i];
                l = __fadd_rn(l, __fmul_rn(r[i], r[i]));
            }
            sSl[(bf ^ 1) * 512 + dg * 128 + vv] = l;
        }
        __syncthreads();
    }

    // ---- loss block-reduce (fp32 shfl, double combine) -> one atomic/CTA ----
#pragma unroll
    for (int o = 16; o; o >>= 1) lsumf += __shfl_down_sync(0xffffffffu, lsumf, o);
    if ((tid & 31) == 0) red[tid >> 5] = (double)lsumf;
    __syncthreads();
    if (tid == 0) {
        double t = 0.0;
#pragma unroll
        for (int w = 0; w < 16; w++) t += red[w];
        atomicAdd(&g_loss, t);
        __threadfence();
        unsigned done = atomicAdd(&g_done, 1u);
        if (done == (unsigned)(gridDim.x - 1)) {
            if (write_extras)
                out[LOSS_OFF] = (float)(0.25 * g_loss / (double)N_ELEMS);
            g_loss = 0.0;
            g_done = 0u;
        }
    }
}

extern "C" void kernel_launch(void* const* d_in, const int* in_sizes, int n_in,
                              void* d_out, int out_size) {
    const float* in  = (const float*)d_in[0];
    const float* emb = (const float*)d_in[1];
    if (n_in >= 2 && in_sizes[0] == K * D && in_sizes[1] == N_ELEMS) {
        const float* t = in; in = emb; emb = t;
    }
    float* out = (float*)d_out;

    cudaFuncSetAttribute(k_main, cudaFuncAttributeMaxDynamicSharedMemorySize, SMEM_BYTES);

    const int extras = (out_size > N_ELEMS) ? 1 : 0;

    k_main<<<NCTA, THREADS, SMEM_BYTES>>>(in, emb, out, extras);
}